// round 17
// baseline (speedup 1.0000x reference)
#include <cuda_runtime.h>
#include <cuda_fp16.h>
#include <math.h>
#include <stdint.h>

#define RTOK 2048
#define DIM  1024
#define NH   16
#define HDIM 64
#define MLPD 4096
#define NBH  32
#define SEQ  1024

// ------------------------- scratch (device globals) -------------------------
__device__ float g_x[RTOK * DIM];
__device__ __align__(128) __half g_a0[RTOK * DIM];
__device__ __align__(128) __half g_h0[RTOK * MLPD];
__device__ __align__(128) __half g_q0[RTOK * DIM];
__device__ __align__(128) __half g_k0[RTOK * DIM];
__device__ __align__(128) __half g_v0[RTOK * DIM];
__device__ __align__(128) __half g_wq0[3*DIM*DIM];
__device__ __align__(128) __half g_wo0[DIM*DIM];
__device__ __align__(128) __half g_w10[MLPD*DIM];
__device__ __align__(128) __half g_w20[DIM*MLPD];

// ------------------------- helpers -------------------------
__device__ __forceinline__ uint32_t smem_u32(const void* p) {
    uint32_t a;
    asm("{ .reg .u64 t; cvta.to.shared.u64 t, %1; cvt.u32.u64 %0, t; }" : "=r"(a) : "l"(p));
    return a;
}
__device__ __forceinline__ uint32_t sw128(uint32_t off) { return off ^ ((off >> 3) & 0x70); }

__device__ __forceinline__ size_t packed_off(int row, int col, int K) {
    int rb = row >> 7, kc = col >> 6;
    uint32_t off = ((uint32_t)(row & 127) << 7) | ((uint32_t)(col & 63) << 1);
    off = off ^ ((off >> 3) & 0x70);
    return ((size_t)(rb * (K >> 6) + kc) << 14) + off;
}

__device__ __forceinline__ void mbar_init(uint32_t a, uint32_t cnt) {
    asm volatile("mbarrier.init.shared.b64 [%0], %1;" :: "r"(a), "r"(cnt) : "memory");
}
__device__ __forceinline__ void mbar_expect_tx(uint32_t a, uint32_t bytes) {
    asm volatile("mbarrier.arrive.expect_tx.shared.b64 _, [%0], %1;" :: "r"(a), "r"(bytes) : "memory");
}
__device__ __forceinline__ void mbar_wait(uint32_t a, uint32_t parity) {
    asm volatile(
        "{\n\t.reg .pred P1;\n\t"
        "LAB_WAIT_%=:\n\t"
        "mbarrier.try_wait.parity.acquire.cta.shared::cta.b64 P1, [%0], %1, 0x989680;\n\t"
        "@P1 bra.uni LAB_DONE_%=;\n\t"
        "bra.uni LAB_WAIT_%=;\n\t"
        "LAB_DONE_%=:\n\t}"
        :: "r"(a), "r"(parity) : "memory");
}
__device__ __forceinline__ void bulk_g2s(uint32_t dst, const void* src, uint32_t bytes, uint32_t mbar) {
    asm volatile(
        "cp.async.bulk.shared::cta.global.mbarrier::complete_tx::bytes [%0], [%1], %2, [%3];"
        :: "r"(dst), "l"(src), "r"(bytes), "r"(mbar) : "memory");
}
__device__ __forceinline__ void ldsm4(uint32_t* r, uint32_t addr) {
    asm volatile("ldmatrix.sync.aligned.m8n8.x4.shared.b16 {%0,%1,%2,%3}, [%4];"
                 : "=r"(r[0]), "=r"(r[1]), "=r"(r[2]), "=r"(r[3]) : "r"(addr));
}
__device__ __forceinline__ void ldsm4t(uint32_t* r, uint32_t addr) {
    asm volatile("ldmatrix.sync.aligned.m8n8.x4.trans.shared.b16 {%0,%1,%2,%3}, [%4];"
                 : "=r"(r[0]), "=r"(r[1]), "=r"(r[2]), "=r"(r[3]) : "r"(addr));
}
__device__ __forceinline__ void mma16816(float* c, const uint32_t* a, const uint32_t* b) {
    asm volatile(
        "mma.sync.aligned.m16n8k16.row.col.f32.f16.f16.f32 "
        "{%0,%1,%2,%3}, {%4,%5,%6,%7}, {%8,%9}, {%0,%1,%2,%3};"
        : "+f"(c[0]), "+f"(c[1]), "+f"(c[2]), "+f"(c[3])
        : "r"(a[0]), "r"(a[1]), "r"(a[2]), "r"(a[3]), "r"(b[0]), "r"(b[1]));
}
__device__ __forceinline__ float ex2(float x) {
    float y; asm("ex2.approx.f32 %0, %1;" : "=f"(y) : "f"(x)); return y;
}
__device__ __forceinline__ uint32_t hpack_hi(float x, float y) {
    __half2 t(__float2half_rn(x), __float2half_rn(y));
    return *reinterpret_cast<uint32_t*>(&t);
}

#define TILE_BYTES  16384
#define G_STAGE     65536
#define SM_TILES    1024
#define NSTAGE      3
#define SM_TOTAL    (SM_TILES + NSTAGE * G_STAGE)
#define GRID_P      128

// -------- persistent fp16 GEMM, tile 128x128, K-chunk 128, cross-tile 3-stage pipe -----
// epi: 0 fp32; 1 +bias+Res fp32; 2 +bias GELU -> fp16; 3 QKV per-head -> fp16
__global__ __launch_bounds__(256, 1) void gemm_tc(
    const char* __restrict__ A, const char* __restrict__ B,
    const float* __restrict__ bias, const float* __restrict__ Res,
    float* __restrict__ Cf, char* __restrict__ C0,
    char* __restrict__ K0o, char* __restrict__ V0o,
    int N, int K, int epi)
{
    extern __shared__ char smem[];
    uint32_t sb = smem_u32(smem);
    int tid = threadIdx.x, wid = tid >> 5, lane = tid & 31;
    int warp_m = (wid >> 1) * 32, warp_n = (wid & 1) * 64;
    const int nx = N >> 7;
    const int NC = K >> 7;
    const int NC64 = K >> 6;
    const int TPC = ((RTOK >> 7) * nx) >> 7;    // tiles per CTA (grid = 128)
    const int t0 = blockIdx.x * TPC;
    const int total_chunks = TPC * NC;

    if (tid == 0) { mbar_init(sb, 1); mbar_init(sb + 8, 1); mbar_init(sb + 16, 1); }
    __syncthreads();

    auto load_chunk = [&](int fc, int s) {
        int tile = t0 + fc / NC;
        int c = fc % NC;
        int mb0 = tile / nx, nb0 = tile % nx;
        size_t abase = ((size_t)(mb0 * NC64)) << 14;
        size_t bbase = ((size_t)(nb0 * NC64)) << 14;
        size_t go = (size_t)c << 15;
        uint32_t mbr = sb + s * 8;
        uint32_t dst = sb + SM_TILES + s * G_STAGE;
        mbar_expect_tx(mbr, G_STAGE);
        bulk_g2s(dst,         A + abase + go, 32768, mbr);
        bulk_g2s(dst + 32768, B + bbase + go, 32768, mbr);
    };

    if (tid == 0) { load_chunk(0, 0); load_chunk(1, 1); }

    int a_row = warp_m + (lane & 15);
    int a_ks  = (lane >> 4) << 4;
    int b_nr  = warp_n + ((lane >> 4) << 3) + (lane & 7);
    int b_ks  = ((lane >> 3) & 1) << 4;

    uint32_t aA[2][2][4], bF[2][4][4];
    int stage = 0, phase = 0;

    for (int t = 0; t < TPC; t++) {
        float acc[2][8][4];
#pragma unroll
        for (int i = 0; i < 2; i++)
#pragma unroll
            for (int j = 0; j < 8; j++)
#pragma unroll
                for (int q = 0; q < 4; q++) acc[i][j][q] = 0.f;

        for (int c = 0; c < NC; c++) {
            int fc = t * NC + c;
            mbar_wait(sb + stage * 8, phase);
            if (tid == 0 && fc + 2 < total_chunks) {
                int s2 = stage + 2; if (s2 >= NSTAGE) s2 -= NSTAGE;
                load_chunk(fc + 2, s2);
            }

            uint32_t base = sb + SM_TILES + stage * G_STAGE;

            auto load_frags = [&](int ks, int buf) {
                uint32_t asub = (uint32_t)(ks >> 2) * TILE_BYTES;
                int ks2 = ks & 3;
#pragma unroll
                for (int mi = 0; mi < 2; mi++) {
                    uint32_t off = sw128((uint32_t)(a_row + mi * 16) * 128 + ks2 * 32 + a_ks);
                    ldsm4(aA[buf][mi], base + asub + off);
                }
#pragma unroll
                for (int nj = 0; nj < 4; nj++) {
                    uint32_t boff = sw128((uint32_t)(b_nr + nj * 16) * 128 + ks2 * 32 + b_ks);
                    ldsm4(bF[buf][nj], base + 32768 + asub + boff);
                }
            };

            load_frags(0, 0);
#pragma unroll
            for (int ks = 0; ks < 8; ks++) {
                int cur = ks & 1;
                if (ks < 7) load_frags(ks + 1, cur ^ 1);
#pragma unroll
                for (int nj = 0; nj < 4; nj++)
#pragma unroll
                    for (int mi = 0; mi < 2; mi++)
#pragma unroll
                        for (int nf = 0; nf < 2; nf++)
                            mma16816(acc[mi][nj * 2 + nf], aA[cur][mi], bF[cur][nj] + 2 * nf);
            }
            __syncthreads();
            if (++stage == NSTAGE) { stage = 0; phase ^= 1; }
        }

        // ---- epilogue for tile t (overlaps with in-flight loads of next tile) ----
        int tile = t0 + t;
        int m0 = (tile / nx) << 7, n0 = (tile % nx) << 7;
        int mrow = m0 + warp_m + (lane >> 2);
        int ncol = n0 + warp_n + (lane & 3) * 2;
#pragma unroll
        for (int mi = 0; mi < 2; mi++) {
#pragma unroll
            for (int nj = 0; nj < 8; nj++) {
#pragma unroll
                for (int h = 0; h < 2; h++) {
                    int m = mrow + mi * 16 + h * 8;
                    int n = ncol + nj * 8;
                    float v0 = acc[mi][nj][2 * h];
                    float v1 = acc[mi][nj][2 * h + 1];
                    if (epi == 0) {
                        *reinterpret_cast<float2*>(Cf + (size_t)m * N + n) = make_float2(v0, v1);
                    } else if (epi == 1) {
                        size_t off = (size_t)m * N + n;
                        float2 r = *reinterpret_cast<const float2*>(Res + off);
                        *reinterpret_cast<float2*>(Cf + off) =
                            make_float2(v0 + bias[n] + r.x, v1 + bias[n + 1] + r.y);
                    } else if (epi == 2) {
                        float t0f = v0 + bias[n], t1f = v1 + bias[n + 1];
                        float g0 = 0.5f * t0f * (1.0f + erff(t0f * 0.70710678118654752f));
                        float g1 = 0.5f * t1f * (1.0f + erff(t1f * 0.70710678118654752f));
                        size_t po = packed_off(m, n, N);
                        *reinterpret_cast<uint32_t*>(C0 + po) = hpack_hi(g0, g1);
                    } else {
                        int sel = n >> 10;
                        int hh  = (n >> 6) & 15;
                        int d   = n & 63;
                        int bb  = m >> 10;
                        int qq  = m & 1023;
                        int blk = ((bb * 16 + hh) * 8) + (qq >> 7);
                        uint32_t off = (uint32_t)(qq & 127) * 128 + d * 2;
                        off ^= (off >> 3) & 0x70;
                        size_t po = ((size_t)blk << 14) + off;
                        char* D = (sel == 0) ? C0 : (sel == 1) ? K0o : V0o;
                        *reinterpret_cast<uint32_t*>(D + po) = hpack_hi(v0, v1);
                    }
                }
            }
        }
    }
}

// ------------------------- flash attention (plain fp16, frag ping-pong) ----------------
#define FL_STAGE 32768
#define FL_SMQ   1024
#define FL_SMKV  (1024 + 16384)
#define FL_TOTAL (1024 + 16384 + 3 * 32768)

__global__ __launch_bounds__(256, 1) void flash_kernel(
    const char* __restrict__ Q0,
    const char* __restrict__ K0, const char* __restrict__ V0,
    char* __restrict__ O0)
{
    extern __shared__ char smem[];
    uint32_t sb = smem_u32(smem);
    int tid = threadIdx.x, wid = tid >> 5, lane = tid & 31;
    int qb = blockIdx.x, bh = blockIdx.y;
    const float SCALE_LOG2E = 0.03125f * 1.44269504088896341f;

    if (tid == 0) {
        mbar_init(sb, 1); mbar_init(sb + 8, 1); mbar_init(sb + 16, 1); mbar_init(sb + 24, 1);
    }
    __syncthreads();

    auto load_chunk = [&](int j, int s) {
        uint32_t mb = sb + s * 8;
        uint32_t dst = sb + FL_SMKV + s * FL_STAGE;
        size_t go = ((size_t)(bh * 8 + j)) << 14;
        mbar_expect_tx(mb, FL_STAGE);
        bulk_g2s(dst,         K0 + go, TILE_BYTES, mb);
        bulk_g2s(dst + 16384, V0 + go, TILE_BYTES, mb);
    };

    if (tid == 0) {
        size_t qo = ((size_t)(bh * 8 + qb)) << 14;
        mbar_expect_tx(sb + 24, 16384);
        bulk_g2s(sb + FL_SMQ, Q0 + qo, TILE_BYTES, sb + 24);
        load_chunk(0, 0);
        load_chunk(1, 1);
    }

    mbar_wait(sb + 24, 0);
    uint32_t aQ[4][4];
    {
        int a_row = wid * 16 + (lane & 15);
        int a_ks  = (lane >> 4) << 4;
#pragma unroll
        for (int ks = 0; ks < 4; ks++) {
            uint32_t off = sw128((uint32_t)a_row * 128 + ks * 32 + a_ks);
            ldsm4(aQ[ks], sb + FL_SMQ + off);
        }
    }

    float acc_o[8][4];
#pragma unroll
    for (int i = 0; i < 8; i++)
#pragma unroll
        for (int q = 0; q < 4; q++) acc_o[i][q] = 0.f;
    float m0 = -1e30f, m1 = -1e30f, l0 = 0.f, l1 = 0.f;

    int b_nr = (lane >> 4) * 8 + (lane & 7);
    int b_ks = ((lane >> 3) & 1) << 4;
    int v_row = lane & 15;
    int v_cs  = (lane >> 4) << 4;

    int stage = 0, phase = 0;
    for (int j = 0; j < 8; j++) {
        mbar_wait(sb + stage * 8, phase);
        if (tid == 0 && j + 2 < 8) {
            int s2 = stage + 2; if (s2 >= NSTAGE) s2 -= NSTAGE;
            load_chunk(j + 2, s2);
        }

        uint32_t kb = sb + FL_SMKV + stage * FL_STAGE;
        uint32_t vb = kb + 16384;

        float p[16][4];
#pragma unroll
        for (int i = 0; i < 16; i++)
#pragma unroll
            for (int q = 0; q < 4; q++) p[i][q] = 0.f;

        {
            uint32_t kfr[2][4];
            ldsm4(kfr[0], kb + sw128((uint32_t)b_nr * 128 + b_ks));
#pragma unroll
            for (int it = 0; it < 32; it++) {
                int nt = it >> 2, ks = it & 3;
                int cur = it & 1;
                if (it + 1 < 32) {
                    int nt2 = (it + 1) >> 2, ks2 = (it + 1) & 3;
                    uint32_t off = sw128((uint32_t)(nt2 * 16 + b_nr) * 128 + ks2 * 32 + b_ks);
                    ldsm4(kfr[cur ^ 1], kb + off);
                }
#pragma unroll
                for (int nf = 0; nf < 2; nf++)
                    mma16816(p[nt * 2 + nf], aQ[ks], kfr[cur] + 2 * nf);
            }
        }

        float cm0 = -1e30f, cm1 = -1e30f;
#pragma unroll
        for (int i = 0; i < 16; i++) {
            cm0 = fmaxf(cm0, fmaxf(p[i][0], p[i][1]));
            cm1 = fmaxf(cm1, fmaxf(p[i][2], p[i][3]));
        }
        cm0 = fmaxf(cm0, __shfl_xor_sync(0xffffffffu, cm0, 1));
        cm0 = fmaxf(cm0, __shfl_xor_sync(0xffffffffu, cm0, 2));
        cm1 = fmaxf(cm1, __shfl_xor_sync(0xffffffffu, cm1, 1));
        cm1 = fmaxf(cm1, __shfl_xor_sync(0xffffffffu, cm1, 2));
        float mn0 = fmaxf(m0, cm0 * SCALE_LOG2E);
        float mn1 = fmaxf(m1, cm1 * SCALE_LOG2E);
        float al0 = ex2(m0 - mn0), al1 = ex2(m1 - mn1);
        m0 = mn0; m1 = mn1;

        float sum0 = 0.f, sum1 = 0.f;
#pragma unroll
        for (int i = 0; i < 16; i++) {
            p[i][0] = ex2(p[i][0] * SCALE_LOG2E - m0); sum0 += p[i][0];
            p[i][1] = ex2(p[i][1] * SCALE_LOG2E - m0); sum0 += p[i][1];
            p[i][2] = ex2(p[i][2] * SCALE_LOG2E - m1); sum1 += p[i][2];
            p[i][3] = ex2(p[i][3] * SCALE_LOG2E - m1); sum1 += p[i][3];
        }
        sum0 += __shfl_xor_sync(0xffffffffu, sum0, 1);
        sum0 += __shfl_xor_sync(0xffffffffu, sum0, 2);
        sum1 += __shfl_xor_sync(0xffffffffu, sum1, 1);
        sum1 += __shfl_xor_sync(0xffffffffu, sum1, 2);
        l0 = al0 * l0 + sum0;
        l1 = al1 * l1 + sum1;

#pragma unroll
        for (int i = 0; i < 8; i++) {
            acc_o[i][0] *= al0; acc_o[i][1] *= al0;
            acc_o[i][2] *= al1; acc_o[i][3] *= al1;
        }

        {
            uint32_t vfr[2][4];
            ldsm4t(vfr[0], vb + sw128((uint32_t)v_row * 128 + v_cs));
            uint32_t phi[4];
#pragma unroll
            for (int it = 0; it < 32; it++) {
                int kk = it >> 2, vt = it & 3;
                int cur = it & 1;
                if (vt == 0) {
                    phi[0] = hpack_hi(p[kk*2][0],   p[kk*2][1]);
                    phi[1] = hpack_hi(p[kk*2][2],   p[kk*2][3]);
                    phi[2] = hpack_hi(p[kk*2+1][0], p[kk*2+1][1]);
                    phi[3] = hpack_hi(p[kk*2+1][2], p[kk*2+1][3]);
                }
                if (it + 1 < 32) {
                    int kk2 = (it + 1) >> 2, vt2 = (it + 1) & 3;
                    uint32_t off = sw128((uint32_t)(kk2 * 16 + v_row) * 128 + vt2 * 32 + v_cs);
                    ldsm4t(vfr[cur ^ 1], vb + off);
                }
#pragma unroll
                for (int nf = 0; nf < 2; nf++)
                    mma16816(acc_o[vt * 2 + nf], phi, vfr[cur] + 2 * nf);
            }
        }
        __syncthreads();
        if (++stage == NSTAGE) { stage = 0; phase ^= 1; }
    }

    float inv0 = 1.f / l0, inv1 = 1.f / l1;
    int bb = bh >> 4, hh = bh & 15;
    int grow = bb * SEQ + qb * 128 + wid * 16 + (lane >> 2);
#pragma unroll
    for (int f = 0; f < 8; f++) {
        int col = hh * 64 + f * 8 + (lane & 3) * 2;
        float x0 = acc_o[f][0] * inv0, y0 = acc_o[f][1] * inv0;
        float x1 = acc_o[f][2] * inv1, y1 = acc_o[f][3] * inv1;
        size_t po0 = packed_off(grow, col, DIM);
        size_t po1 = packed_off(grow + 8, col, DIM);
        *reinterpret_cast<uint32_t*>(O0 + po0) = hpack_hi(x0, y0);
        *reinterpret_cast<uint32_t*>(O0 + po1) = hpack_hi(x1, y1);
    }
}

// ------------------------- reductions -------------------------
__device__ __forceinline__ float warp_sum(float v) {
#pragma unroll
    for (int o = 16; o; o >>= 1) v += __shfl_xor_sync(0xffffffffu, v, o);
    return v;
}

// ------------------------- layernorm -> packed fp16 -------------------------
__global__ __launch_bounds__(256) void ln_split_kernel(
    const float* __restrict__ X, const float* __restrict__ G,
    const float* __restrict__ B, char* __restrict__ Y0)
{
    __shared__ float red[8];
    int row = blockIdx.x;
    int tid = threadIdx.x;
    int lane = tid & 31, wid = tid >> 5;

    float4 v = reinterpret_cast<const float4*>(X + (size_t)row * DIM)[tid];
    float s = v.x + v.y + v.z + v.w;
    s = warp_sum(s);
    if (lane == 0) red[wid] = s;
    __syncthreads();
    if (wid == 0) {
        float t = (lane < 8) ? red[lane] : 0.f;
        t = warp_sum(t);
        if (lane == 0) red[0] = t;
    }
    __syncthreads();
    float mu = red[0] * (1.0f / DIM);
    __syncthreads();

    float4 d;
    d.x = v.x - mu; d.y = v.y - mu; d.z = v.z - mu; d.w = v.w - mu;
    float sq = d.x*d.x + d.y*d.y + d.z*d.z + d.w*d.w;
    sq = warp_sum(sq);
    if (lane == 0) red[wid] = sq;
    __syncthreads();
    if (wid == 0) {
        float t = (lane < 8) ? red[lane] : 0.f;
        t = warp_sum(t);
        if (lane == 0) red[0] = t;
    }
    __syncthreads();
    float rs = rsqrtf(red[0] * (1.0f / DIM) + 1e-5f);

    float4 g4 = reinterpret_cast<const float4*>(G)[tid];
    float4 b4 = reinterpret_cast<const float4*>(B)[tid];
    float y[4];
    y[0] = d.x * rs * g4.x + b4.x;
    y[1] = d.y * rs * g4.y + b4.y;
    y[2] = d.z * rs * g4.z + b4.z;
    y[3] = d.w * rs * g4.w + b4.w;

    size_t po = packed_off(row, tid * 4, DIM);
    *reinterpret_cast<uint2*>(Y0 + po) = make_uint2(hpack_hi(y[0], y[1]), hpack_hi(y[2], y[3]));
}

// ------------------------- weight transpose -> plain fp16 packed ----------------------
__global__ __launch_bounds__(256) void wsplit_dual(
    const float* __restrict__ Wa, char* __restrict__ Ta, int Ka, int Na,
    const float* __restrict__ Wb, char* __restrict__ Tb, int Kb, int Nb)
{
    const float* W; char* T; int K, N, n0, k0;
    if (blockIdx.z == 0) {
        W = Wa; T = Ta; K = Ka; N = Na;
        n0 = blockIdx.x * 32; k0 = blockIdx.y * 32;
    } else {
        W = Wb; T = Tb; K = Kb; N = Nb;
        n0 = blockIdx.y * 32; k0 = blockIdx.x * 32;
    }
    if (n0 >= N || k0 >= K) return;

    __shared__ float t[32][33];
    int c = threadIdx.x & 31, r = threadIdx.x >> 5;
#pragma unroll
    for (int rr = 0; rr < 32; rr += 8)
        t[r + rr][c] = W[(size_t)(k0 + r + rr) * N + n0 + c];
    __syncthreads();
    int tx = threadIdx.x & 7;
    int ty = threadIdx.x >> 3;
    int n = n0 + ty, k = k0 + tx * 4;
    float v0 = t[tx*4+0][ty], v1 = t[tx*4+1][ty], v2 = t[tx*4+2][ty], v3 = t[tx*4+3][ty];
    size_t po = packed_off(n, k, K);
    *reinterpret_cast<uint2*>(T + po) = make_uint2(hpack_hi(v0, v1), hpack_hi(v2, v3));
}

// ------------------------- launch -------------------------
extern "C" void kernel_launch(void* const* d_in, const int* in_sizes, int n_in,
                              void* d_out, int out_size)
{
    const float* x     = (const float*)d_in[0];
    const float* ln1_g = (const float*)d_in[1];
    const float* ln1_b = (const float*)d_in[2];
    const float* w_qkv = (const float*)d_in[3];
    const float* w_o   = (const float*)d_in[4];
    const float* b_o   = (const float*)d_in[5];
    const float* ln2_g = (const float*)d_in[6];
    const float* ln2_b = (const float*)d_in[7];
    const float* w1    = (const float*)d_in[8];
    const float* b1    = (const float*)d_in[9];
    const float* w2    = (const float*)d_in[10];
    const float* b2    = (const float*)d_in[11];

    float *gx;
    char *a0, *h0, *q0, *k0, *v0;
    char *wq0, *wo0, *w10, *w20;
    cudaGetSymbolAddress((void**)&gx,  g_x);
    cudaGetSymbolAddress((void**)&a0,  g_a0);
    cudaGetSymbolAddress((void**)&h0,  g_h0);
    cudaGetSymbolAddress((void**)&q0,  g_q0);
    cudaGetSymbolAddress((void**)&k0,  g_k0);
    cudaGetSymbolAddress((void**)&v0,  g_v0);
    cudaGetSymbolAddress((void**)&wq0, g_wq0);
    cudaGetSymbolAddress((void**)&wo0, g_wo0);
    cudaGetSymbolAddress((void**)&w10, g_w10);
    cudaGetSymbolAddress((void**)&w20, g_w20);

    cudaFuncSetAttribute(gemm_tc, cudaFuncAttributeMaxDynamicSharedMemorySize, SM_TOTAL);
    cudaFuncSetAttribute(flash_kernel, cudaFuncAttributeMaxDynamicSharedMemorySize, FL_TOTAL);

    wsplit_dual<<<dim3(96, 32, 2), 256>>>(w_qkv, wq0, DIM, 3 * DIM,
                                          w_o, wo0, DIM, DIM);
    wsplit_dual<<<dim3(128, 32, 2), 256>>>(w1, w10, DIM, MLPD,
                                           w2, w20, MLPD, DIM);

    for (int layer = 0; layer < 4; layer++) {
        const float* xin = (layer == 0) ? x : gx;

        // --- attention ---
        ln_split_kernel<<<RTOK, 256>>>(xin, ln1_g, ln1_b, a0);
        gemm_tc<<<GRID_P, 256, SM_TOTAL>>>(
            a0, wq0, nullptr, nullptr, nullptr, q0,
            k0, v0, 3 * DIM, DIM, 3);
        flash_kernel<<<dim3(8, NBH), 256, FL_TOTAL>>>(
            q0, k0, v0, a0);
        gemm_tc<<<GRID_P, 256, SM_TOTAL>>>(
            a0, wo0, b_o, xin, gx, nullptr,
            nullptr, nullptr, DIM, DIM, 1);

        // --- MLP ---
        ln_split_kernel<<<RTOK, 256>>>(gx, ln2_g, ln2_b, a0);
        gemm_tc<<<GRID_P, 256, SM_TOTAL>>>(
            a0, w10, b1, nullptr, nullptr, h0,
            nullptr, nullptr, MLPD, DIM, 2);
        float* outp = (layer == 3) ? (float*)d_out : gx;
        gemm_tc<<<GRID_P, 256, SM_TOTAL>>>(
            h0, w20, b2, gx, outp, nullptr,
            nullptr, nullptr, DIM, MLPD, 1);
    }
}